// round 6
// baseline (speedup 1.0000x reference)
#include <cuda_runtime.h>

// LbpBlock: out = concat([x, pad(x_cat)], ch axis)
//   y[n,o,h,w] = sum_c x[n,c,h,w]*conv_w[o,c]   (c=3, o=64)
//   x_cat interior = sum_l H(y_c - y_shift_l) * exp(w[o,l]), zero border.
// x: (8,3,256,256) f32, conv_w: (64,3), w: (64,8) -> out: (8,67,256,256)
//
// R6 design: 32-thread blocks (one warp), warp-private 8x32 tile + 10x34
// y-halo slice in block-private smem. No cross-warp coupling anywhere:
// __syncthreads degenerates to a 3-cycle single-warp barrier. 2048 blocks,
// single wave, ~14 independent warps/SM.

#define NN   8
#define CIN  3
#define OCH  64
#define HH   256
#define WW   256
#define TH   8
#define TW   32
#define NCHUNK 16                // 4 channels per chunk
#define HALO_H 10
#define HALO_W 34
#define HALO_N (HALO_H * HALO_W) // 340
#define XRN  11                  // ceil(340/32)
#define YP   42                  // f4 row pitch: 42*16 mod 128 = 32 (row spread)
#define PLANE (HH * WW)

__device__ __forceinline__ int sw(int c) { return c + (c >> 3); }

__global__ __launch_bounds__(32, 16)
void lbp_main(const float* __restrict__ x,
              const float* __restrict__ cw,
              const float* __restrict__ w,
              float* __restrict__ out)
{
    __shared__ float4 ysl[HALO_H][YP];   // 6720 B  warp-private y (4ch packed)
    __shared__ float  sew[OCH][8];       // 2048 B  exp(w)
    __shared__ float4 scw[OCH];          // 1024 B  conv_w rows

    const int tid = threadIdx.x;
    const int n   = blockIdx.z;
    const int h0  = blockIdx.y * TH;
    const int w0  = blockIdx.x * TW;

    // ---- per-block weight tables ----
    for (int i = tid; i < OCH * 8; i += 32)
        sew[i >> 3][i & 7] = __expf(w[i]);
    for (int i = tid; i < OCH; i += 32)
        scw[i] = make_float4(cw[3 * i], cw[3 * i + 1], cw[3 * i + 2], 0.f);

    // ---- x halo in registers (<= 11 px / thread) ----
    float xr[XRN][3];
    int   soff[XRN];                     // y-smem f4 index per owned halo px
    #pragma unroll
    for (int k = 0; k < XRN; k++) {
        const int p = tid + k * 32;
        const int r = p / HALO_W;
        const int c = p - r * HALO_W;
        soff[k] = r * YP + sw(c);
        float v0 = 0.f, v1 = 0.f, v2 = 0.f;
        if (p < HALO_N) {
            const int gh = h0 - 1 + r;
            const int gw = w0 - 1 + c;
            if ((unsigned)gh < HH && (unsigned)gw < WW) {
                const int b = (n * CIN * HH + gh) * WW + gw;
                v0 = x[b];
                v1 = x[b + PLANE];
                v2 = x[b + 2 * PLANE];
            }
        }
        xr[k][0] = v0; xr[k][1] = v1; xr[k][2] = v2;
    }

    // ---- fused copy: x -> out channels [0,3) for this 8x32 tile ----
    {
        const float4* x4 = (const float4*)(x + n * CIN * PLANE);
        float4*       o4 = (float4*)(out + n * 67 * PLANE);
        #pragma unroll
        for (int j = 0; j < 6; j++) {            // 192 float4 per tile
            const int f   = tid + j * 32;
            const int c   = f >> 6;              // 64 f4 per channel-tile
            const int rem = f & 63;
            const int rr  = rem >> 3;
            const int cc  = rem & 7;
            const int idx = c * (PLANE / 4) + (h0 + rr) * (WW / 4)
                          + (w0 >> 2) + cc;
            o4[idx] = x4[idx];
        }
    }
    __syncthreads();   // weight tables visible (single-warp barrier: ~3 cyc)

    // thread -> 2 rows x 4 cols micro-tile
    const int mcol = tid & 7;                // col group (4 px)
    const int mrg  = tid >> 3;               // row pair (0..3)
    const int hr0  = 2 * mrg;                // top window halo row
    const int sc0  = 4 * mcol;               // window halo col base
    const int oh0  = h0 + 2 * mrg;
    const int owb  = w0 + 4 * mcol;

    for (int ch = 0; ch < NCHUNK; ch++) {
        const int o0 = 4 * ch;

        // ---- phase 1: y halo for this chunk (register FMA -> STS) ----
        {
            const float4 c0 = scw[o0],     c1 = scw[o0 + 1];
            const float4 c2 = scw[o0 + 2], c3 = scw[o0 + 3];
            #pragma unroll
            for (int k = 0; k < XRN; k++) {
                if (tid + k * 32 < HALO_N) {
                    const float a = xr[k][0], b = xr[k][1], d = xr[k][2];
                    float4 v;
                    v.x = fmaf(d, c0.z, fmaf(b, c0.y, a * c0.x));
                    v.y = fmaf(d, c1.z, fmaf(b, c1.y, a * c1.x));
                    v.z = fmaf(d, c2.z, fmaf(b, c2.y, a * c2.x));
                    v.w = fmaf(d, c3.z, fmaf(b, c3.y, a * c3.x));
                    ((float4*)ysl)[soff[k]] = v;
                }
            }
        }
        __syncthreads();

        #define LDS2(r, c, p) (((const float2*)&ysl[r][sw(c)])[p])

        #pragma unroll
        for (int p = 0; p < 2; p++) {        // channel pair within chunk
            // rolling 3-row window of float2 (2 channels)
            float2 t0[6], t1[6], t2[6];
            #pragma unroll
            for (int c = 0; c < 6; c++) {
                t0[c] = LDS2(hr0,     sc0 + c, p);
                t1[c] = LDS2(hr0 + 1, sc0 + c, p);
                t2[c] = LDS2(hr0 + 2, sc0 + c, p);
            }

            const int cA = o0 + 2 * p;       // first channel of pair
            float e0[8], e1[8];
            {
                const float4 u0 = *(const float4*)&sew[cA][0];
                const float4 u1 = *(const float4*)&sew[cA][4];
                e0[0] = u0.x; e0[1] = u0.y; e0[2] = u0.z; e0[3] = u0.w;
                e0[4] = u1.x; e0[5] = u1.y; e0[6] = u1.z; e0[7] = u1.w;
                const float4 v0 = *(const float4*)&sew[cA + 1][0];
                const float4 v1 = *(const float4*)&sew[cA + 1][4];
                e1[0] = v0.x; e1[1] = v0.y; e1[2] = v0.z; e1[3] = v0.w;
                e1[4] = v1.x; e1[5] = v1.y; e1[6] = v1.z; e1[7] = v1.w;
            }

            #pragma unroll
            for (int pr = 0; pr < 2; pr++) { // the 2 pixel rows
                if (pr == 1) {
                    #pragma unroll
                    for (int c = 0; c < 6; c++) {
                        t0[c] = t1[c];
                        t1[c] = t2[c];
                        t2[c] = LDS2(hr0 + 3, sc0 + c, p);
                    }
                }
                const int oh = oh0 + pr;
                const bool hv = ((unsigned)(oh - 1) < (unsigned)(HH - 2));

                float rA[4], rB[4];
                #pragma unroll
                for (int jj = 0; jj < 4; jj++) {
                    const float2 ce = t1[jj + 1];
                    float a0 = 0.f, a1 = 0.f;

                    #define ACC(S, L) { const float2 s_ = (S);   \
                        if (ce.x > s_.x) a0 += e0[L];            \
                        if (ce.y > s_.y) a1 += e1[L]; }

                    // TL, T, TR, L, BL, B, BR, R (reference shift order)
                    ACC(t0[jj    ], 0)
                    ACC(t0[jj + 1], 1)
                    ACC(t0[jj + 2], 2)
                    ACC(t1[jj    ], 3)
                    ACC(t2[jj    ], 4)
                    ACC(t2[jj + 1], 5)
                    ACC(t2[jj + 2], 6)
                    ACC(t1[jj + 2], 7)
                    #undef ACC

                    const int ow = owb + jj;
                    const bool v = hv &&
                        ((unsigned)(ow - 1) < (unsigned)(WW - 2));
                    rA[jj] = v ? a0 : 0.f;
                    rB[jj] = v ? a1 : 0.f;
                }

                // coalesced float4 stores (2 channels x 4 px, 128B/row-octet)
                const int ob = ((n * 67 + 3 + cA) * HH + oh) * WW + owb;
                *(float4*)(out + ob        ) = make_float4(rA[0], rA[1], rA[2], rA[3]);
                *(float4*)(out + ob + PLANE) = make_float4(rB[0], rB[1], rB[2], rB[3]);
            }
        }
        #undef LDS2

        __syncthreads();   // all reads done before next chunk overwrites ysl
    }
}

extern "C" void kernel_launch(void* const* d_in, const int* in_sizes, int n_in,
                              void* d_out, int out_size)
{
    const float* x  = (const float*)d_in[0];
    const float* cw = (const float*)d_in[1];
    const float* w  = (const float*)d_in[2];
    float* out = (float*)d_out;

    dim3 grid(WW / TW, HH / TH, NN);   // (8, 32, 8) = 2048 one-warp blocks
    lbp_main<<<grid, 32>>>(x, cw, w, out);
}